// round 2
// baseline (speedup 1.0000x reference)
#include <cuda_runtime.h>
#include <math.h>

#define NN   100000
#define NE   1600000
#define INC  256
#define HIDD 128
#define HEADS 4
#define CHEAD 32
#define BN_EPS 1e-5f
#define NEG_SLOPE 0.2f

// ---------------- scratch (device globals: no allocs allowed) ----------------
__device__ float g_h   [(size_t)NN*HIDD];   // x @ W_gat
__device__ float g_h1  [(size_t)NN*HIDD];   // post BN1+ELU
__device__ float g_out1[(size_t)NN*HIDD];   // GAT aggregation (pre BN1)
__device__ float g_agg [(size_t)NN*HIDD];   // GIN neighbor sum
__device__ float g_e   [(size_t)NE*HEADS];  // edge logits -> exp numerators
__device__ float g_asrc[NN*HEADS];
__device__ float g_adst[NN*HEADS];
__device__ float g_m   [NN*HEADS];          // segment max
__device__ float g_den [NN*HEADS];          // segment sum of exp
__device__ float g_sum [HIDD];
__device__ float g_sumsq[HIDD];
__device__ float g_scale[HIDD];
__device__ float g_shift[HIDD];
__device__ int   g_src[NE];
__device__ int   g_dst[NE];
__device__ int   g_is64;

// ---------------- helpers ----------------
__device__ __forceinline__ void redAdd4(float* addr, float4 v) {
    asm volatile("red.global.add.v4.f32 [%0], {%1,%2,%3,%4};"
                 :: "l"(addr), "f"(v.x), "f"(v.y), "f"(v.z), "f"(v.w) : "memory");
}

__device__ __forceinline__ void atomicMaxF(float* a, float v) {
    // mixed signed-max / unsigned-min trick: stored bits are always a real float
    if (v >= 0.0f) atomicMax((int*)a, __float_as_int(v));
    else           atomicMin((unsigned int*)a, __float_as_uint(v));
}

__device__ __forceinline__ float lrelu(float x) { return x > 0.0f ? x : NEG_SLOPE * x; }
__device__ __forceinline__ float elu(float x)   { return x > 0.0f ? x : expm1f(x); }

// ---------------- init ----------------
__global__ void k_init() {
    size_t i = (size_t)blockIdx.x * blockDim.x + threadIdx.x;   // exactly NN*HIDD threads
    g_out1[i] = 0.0f;
    g_agg[i]  = 0.0f;
    if (i < (size_t)NN * HEADS) {
        g_den[i] = 0.0f;
        g_m[i]   = __int_as_float(0xff800000);  // -inf
    }
    if (i < HIDD) { g_sum[i] = 0.0f; g_sumsq[i] = 0.0f; }
}

// detect whether edge_index arrived as int64 or int32 (jax x64 ambiguity)
__global__ void k_detect(const long long* __restrict__ ei) {
    __shared__ int ok;
    if (threadIdx.x == 0) ok = 1;
    __syncthreads();
    for (int i = threadIdx.x; i < 1024; i += blockDim.x) {
        long long v = ei[i];
        if (v < 0 || v >= NN) atomicExch(&ok, 0);
    }
    __syncthreads();
    if (threadIdx.x == 0) g_is64 = ok;
}

__global__ void k_edgecvt(const void* __restrict__ eiv) {
    int i = blockIdx.x * blockDim.x + threadIdx.x;
    if (i >= NE) return;
    if (g_is64) {
        const long long* p = (const long long*)eiv;
        g_src[i] = (int)p[i];
        g_dst[i] = (int)p[NE + i];
    } else {
        const int* p = (const int*)eiv;
        g_src[i] = p[i];
        g_dst[i] = p[NE + i];
    }
}

// ---------------- GEMM: C[M,128] = Aeff[M,K] @ B[K,128] ----------------
// mode 0: A = Aext (x), K=INC,  C = g_h            (GEMM1)
// mode 1: A = (1+eps)*g_h1 + g_agg, K=HIDD, C=Cext (GEMM2, GIN fusion)
__global__ __launch_bounds__(256) void k_gemm(
    const float* __restrict__ Aext, const float* __restrict__ B,
    float* __restrict__ Cext, const float* __restrict__ epsPtr, int mode)
{
    __shared__ float As[16][128];
    __shared__ float Bs[16][128];
    int t  = threadIdx.x;
    int tx = t & 15, ty = t >> 4;
    int blockM = blockIdx.x * 128;

    const float* A  = (mode == 0) ? Aext : g_h1;
    const float* A2 = (mode == 0) ? nullptr : g_agg;
    float*       C  = (mode == 0) ? g_h : Cext;
    int          K  = (mode == 0) ? INC : HIDD;
    float ke = 1.0f;
    if (mode == 1) ke = 1.0f + __ldg(epsPtr);

    float acc[8][8];
#pragma unroll
    for (int r = 0; r < 8; r++)
#pragma unroll
        for (int c = 0; c < 8; c++) acc[r][c] = 0.0f;

    for (int kk = 0; kk < K; kk += 16) {
        // load A tile 128x16
#pragma unroll
        for (int i = 0; i < 2; i++) {
            int li = t + i * 256;
            int aRow = li >> 2;
            int aC   = (li & 3) * 4;
            int gRow = blockM + aRow;
            float4 v = make_float4(0.f, 0.f, 0.f, 0.f);
            if (gRow < NN) {
                v = *(const float4*)(A + (size_t)gRow * K + kk + aC);
                if (A2) {
                    float4 w = *(const float4*)(A2 + (size_t)gRow * K + kk + aC);
                    v.x = ke * v.x + w.x; v.y = ke * v.y + w.y;
                    v.z = ke * v.z + w.z; v.w = ke * v.w + w.w;
                }
            }
            As[aC + 0][aRow] = v.x; As[aC + 1][aRow] = v.y;
            As[aC + 2][aRow] = v.z; As[aC + 3][aRow] = v.w;
        }
        // load B tile 16x128
#pragma unroll
        for (int i = 0; i < 2; i++) {
            int li = t + i * 256;
            int bRow = li >> 5;
            int bC   = (li & 31) * 4;
            float4 v = *(const float4*)(B + (size_t)(kk + bRow) * HIDD + bC);
            *(float4*)&Bs[bRow][bC] = v;
        }
        __syncthreads();
#pragma unroll
        for (int k = 0; k < 16; k++) {
            float ra[8], rb[8];
#pragma unroll
            for (int r = 0; r < 8; r++) ra[r] = As[k][ty * 8 + r];
#pragma unroll
            for (int c = 0; c < 8; c++) rb[c] = Bs[k][tx * 8 + c];
#pragma unroll
            for (int r = 0; r < 8; r++)
#pragma unroll
                for (int c = 0; c < 8; c++) acc[r][c] += ra[r] * rb[c];
        }
        __syncthreads();
    }
#pragma unroll
    for (int r = 0; r < 8; r++) {
        int gRow = blockM + ty * 8 + r;
        if (gRow < NN) {
            float4 v0 = make_float4(acc[r][0], acc[r][1], acc[r][2], acc[r][3]);
            float4 v1 = make_float4(acc[r][4], acc[r][5], acc[r][6], acc[r][7]);
            *(float4*)(C + (size_t)gRow * HIDD + tx * 8)     = v0;
            *(float4*)(C + (size_t)gRow * HIDD + tx * 8 + 4) = v1;
        }
    }
}

// ---------------- attention logits per node ----------------
__global__ void k_att(const float* __restrict__ att_s, const float* __restrict__ att_d) {
    int t = blockIdx.x * blockDim.x + threadIdx.x;
    if (t >= NN * HEADS) return;
    int n = t >> 2, head = t & 3;
    const float4* hp  = (const float4*)(g_h + (size_t)n * HIDD + head * CHEAD);
    const float4* asp = (const float4*)(att_s + head * CHEAD);
    const float4* adp = (const float4*)(att_d + head * CHEAD);
    float ss = 0.f, sd = 0.f;
#pragma unroll
    for (int i = 0; i < 8; i++) {
        float4 hv = hp[i], a = asp[i], b = adp[i];
        ss += hv.x * a.x + hv.y * a.y + hv.z * a.z + hv.w * a.w;
        sd += hv.x * b.x + hv.y * b.y + hv.z * b.z + hv.w * b.w;
    }
    g_asrc[t] = ss;
    g_adst[t] = sd;
}

// ---------------- edge pass 1: leaky_relu logits + segment max ----------------
__global__ void k_edge_max() {
    int e = blockIdx.x * blockDim.x + threadIdx.x;
    if (e >= NE) return;
    int s = g_src[e], d = g_dst[e];
    float4 a = *(const float4*)(g_asrc + s * 4);
    float4 b = *(const float4*)(g_adst + d * 4);
    float4 v;
    v.x = lrelu(a.x + b.x); v.y = lrelu(a.y + b.y);
    v.z = lrelu(a.z + b.z); v.w = lrelu(a.w + b.w);
    *(float4*)(g_e + (size_t)e * 4) = v;
    float* m = g_m + d * 4;
    atomicMaxF(m + 0, v.x); atomicMaxF(m + 1, v.y);
    atomicMaxF(m + 2, v.z); atomicMaxF(m + 3, v.w);
}

// ---------------- edge pass 2: exp(e - m), segment sum ----------------
__global__ void k_edge_num() {
    int e = blockIdx.x * blockDim.x + threadIdx.x;
    if (e >= NE) return;
    int d = g_dst[e];
    float4 v = *(const float4*)(g_e + (size_t)e * 4);
    float4 m = *(const float4*)(g_m + d * 4);
    float4 num;
    num.x = expf(v.x - m.x); num.y = expf(v.y - m.y);
    num.z = expf(v.z - m.z); num.w = expf(v.w - m.w);
    *(float4*)(g_e + (size_t)e * 4) = num;
    redAdd4(g_den + d * 4, num);
}

// ---------------- edge pass 3: out1[dst] += alpha * h[src]  (warp/edge) -----
__global__ __launch_bounds__(256) void k_edge_msg() {
    int gw   = (blockIdx.x * blockDim.x + threadIdx.x) >> 5;
    int lane = threadIdx.x & 31;
    int nw   = (gridDim.x * blockDim.x) >> 5;
    for (int e = gw; e < NE; e += nw) {
        int s = g_src[e], d = g_dst[e];
        int head = lane >> 3;
        float num = g_e[(size_t)e * 4 + head];
        float den = g_den[d * 4 + head];
        float alpha = num / den;
        float4 hv = *(const float4*)(g_h + (size_t)s * HIDD + lane * 4);
        redAdd4(g_out1 + (size_t)d * HIDD + lane * 4,
                make_float4(alpha * hv.x, alpha * hv.y, alpha * hv.z, alpha * hv.w));
    }
}

// ---------------- GIN neighbor sum: agg[dst] += h1[src]  (warp/edge) --------
__global__ __launch_bounds__(256) void k_gin_agg() {
    int gw   = (blockIdx.x * blockDim.x + threadIdx.x) >> 5;
    int lane = threadIdx.x & 31;
    int nw   = (gridDim.x * blockDim.x) >> 5;
    for (int e = gw; e < NE; e += nw) {
        int s = g_src[e], d = g_dst[e];
        float4 hv = *(const float4*)(g_h1 + (size_t)s * HIDD + lane * 4);
        redAdd4(g_agg + (size_t)d * HIDD + lane * 4, hv);
    }
}

// ---------------- batch norm ----------------
// mode 0: X = g_out1 ; mode 1: X = Xext (harness out buffer)
__global__ void k_bn_stats(const float* __restrict__ Xext, int mode) {
    const float* X = (mode == 0) ? g_out1 : Xext;
    int c = threadIdx.x;                 // 128 threads = one channel each
    int rowsPer = (NN + gridDim.x - 1) / gridDim.x;
    int r0 = blockIdx.x * rowsPer;
    int r1 = r0 + rowsPer; if (r1 > NN) r1 = NN;
    float s = 0.f, q = 0.f;
    for (int r = r0; r < r1; r++) {
        float v = X[(size_t)r * HIDD + c];
        s += v; q += v * v;
    }
    atomicAdd(&g_sum[c], s);
    atomicAdd(&g_sumsq[c], q);
}

__global__ void k_bn_final(const float* __restrict__ gamma, const float* __restrict__ beta) {
    int c = threadIdx.x;
    float mean = g_sum[c] / (float)NN;
    float var  = g_sumsq[c] / (float)NN - mean * mean;
    float sc   = gamma[c] * rsqrtf(var + BN_EPS);
    g_scale[c] = sc;
    g_shift[c] = beta[c] - mean * sc;
    g_sum[c] = 0.f;                      // leave zeroed for next stats pass
    g_sumsq[c] = 0.f;
}

// mode 0: g_out1 -> g_h1 ; mode 1: Xext -> Yext (out, in place)
__global__ void k_bn_apply_elu(const float* __restrict__ Xext, float* __restrict__ Yext, int mode) {
    const float* X = (mode == 0) ? g_out1 : Xext;
    float*       Y = (mode == 0) ? g_h1   : Yext;
    size_t i = (size_t)blockIdx.x * blockDim.x + threadIdx.x;   // NN*HIDD/4 threads
    int c4 = (int)(i & 31);
    float4 v  = ((const float4*)X)[i];
    float4 sc = ((const float4*)g_scale)[c4];
    float4 sh = ((const float4*)g_shift)[c4];
    float4 o;
    o.x = elu(v.x * sc.x + sh.x);
    o.y = elu(v.y * sc.y + sh.y);
    o.z = elu(v.z * sc.z + sh.z);
    o.w = elu(v.w * sc.w + sh.w);
    ((float4*)Y)[i] = o;
}

// ---------------- launch ----------------
extern "C" void kernel_launch(void* const* d_in, const int* in_sizes, int n_in,
                              void* d_out, int out_size) {
    const float* x         = (const float*)d_in[0];
    const float* W_gat     = (const float*)d_in[1];
    const float* att_src   = (const float*)d_in[2];
    const float* att_dst   = (const float*)d_in[3];
    // d_in[4] = bias_gat  : cancels inside BN1 (per-channel shift) -> unused
    const float* bn1_gamma = (const float*)d_in[5];
    const float* bn1_beta  = (const float*)d_in[6];
    const float* eps_gin   = (const float*)d_in[7];
    const float* lin_W     = (const float*)d_in[8];
    // d_in[9] = lin_b     : cancels inside BN2 -> unused
    const float* bn2_gamma = (const float*)d_in[10];
    const float* bn2_beta  = (const float*)d_in[11];
    const void*  edge_idx  = d_in[12];
    float* out = (float*)d_out;

    // init scratch (exactly NN*HIDD threads)
    k_init<<<(NN * HIDD) / 256, 256>>>();
    k_detect<<<1, 256>>>((const long long*)edge_idx);
    k_edgecvt<<<NE / 256, 256>>>(edge_idx);

    // GEMM1: g_h = x @ W_gat
    k_gemm<<<(NN + 127) / 128, 256>>>(x, W_gat, nullptr, nullptr, 0);

    // attention logits per node
    k_att<<<(NN * HEADS + 255) / 256, 256>>>(att_src, att_dst);

    // segment softmax + message aggregation
    k_edge_max<<<NE / 256, 256>>>();
    k_edge_num<<<NE / 256, 256>>>();
    k_edge_msg<<<4096, 256>>>();

    // BN1 + ELU -> g_h1
    k_bn_stats<<<400, 128>>>(nullptr, 0);
    k_bn_final<<<1, 128>>>(bn1_gamma, bn1_beta);
    k_bn_apply_elu<<<(NN * HIDD / 4) / 256, 256>>>(nullptr, nullptr, 0);

    // GIN aggregation
    k_gin_agg<<<4096, 256>>>();

    // GEMM2 on fused z = (1+eps)*g_h1 + g_agg  -> d_out (pre-BN2)
    k_gemm<<<(NN + 127) / 128, 256>>>(nullptr, lin_W, out, eps_gin, 1);

    // BN2 + ELU in place on d_out
    k_bn_stats<<<400, 128>>>(out, 1);
    k_bn_final<<<1, 128>>>(bn2_gamma, bn2_beta);
    k_bn_apply_elu<<<(NN * HIDD / 4) / 256, 256>>>(out, out, 1);
}

// round 3
// speedup vs baseline: 1.4794x; 1.4794x over previous
#include <cuda_runtime.h>
#include <math.h>

#define NN   100000
#define NE   1600000
#define INC  256
#define HIDD 128
#define HEADS 4
#define CHEAD 32
#define BN_EPS 1e-5f
#define NEG_SLOPE 0.2f
#define SCANB 1024
#define NBLK  ((NN + SCANB - 1) / SCANB)   // 98

// ---------------- scratch (device globals: no allocs allowed) ----------------
__device__ float g_h   [(size_t)NN*HIDD];   // x @ W_gat
__device__ float g_h1  [(size_t)NN*HIDD];   // post BN1+ELU
__device__ float g_out1[(size_t)NN*HIDD];   // GAT aggregation (pre BN1)
__device__ float g_agg [(size_t)NN*HIDD];   // GIN neighbor sum
__device__ float g_asrc[NN*HEADS];
__device__ float g_adst[NN*HEADS];
__device__ float g_sum [HIDD];
__device__ float g_sumsq[HIDD];
__device__ float g_scale[HIDD];
__device__ float g_shift[HIDD];
__device__ int   g_src[NE];
__device__ int   g_dst[NE];
__device__ int   g_esrc[NE];                // CSR: src ids grouped by dst
__device__ int   g_rowptr[NN+1];
__device__ int   g_deg[NN];
__device__ int   g_woff[NN];
__device__ int   g_bsum[NBLK];
__device__ int   g_boff[NBLK];
__device__ int   g_is64;

// ---------------- helpers ----------------
__device__ __forceinline__ float lrelu(float x) { return x > 0.0f ? x : NEG_SLOPE * x; }
__device__ __forceinline__ float elu(float x)   { return x > 0.0f ? x : expm1f(x); }

// ---------------- init ----------------
__global__ void k_init() {
    int i = blockIdx.x * blockDim.x + threadIdx.x;   // >= NN threads
    if (i < NN) { g_deg[i] = 0; g_woff[i] = 0; }
    if (i < HIDD) { g_sum[i] = 0.0f; g_sumsq[i] = 0.0f; }
}

// detect whether edge_index arrived as int64 or int32 (jax x64 ambiguity)
__global__ void k_detect(const long long* __restrict__ ei) {
    __shared__ int ok;
    if (threadIdx.x == 0) ok = 1;
    __syncthreads();
    for (int i = threadIdx.x; i < 1024; i += blockDim.x) {
        long long v = ei[i];
        if (v < 0 || v >= NN) atomicExch(&ok, 0);
    }
    __syncthreads();
    if (threadIdx.x == 0) g_is64 = ok;
}

// convert edges + histogram of dst degrees
__global__ void k_edgecvt(const void* __restrict__ eiv) {
    int i = blockIdx.x * blockDim.x + threadIdx.x;
    if (i >= NE) return;
    int s, d;
    if (g_is64) {
        const long long* p = (const long long*)eiv;
        s = (int)p[i]; d = (int)p[NE + i];
    } else {
        const int* p = (const int*)eiv;
        s = p[i]; d = p[NE + i];
    }
    g_src[i] = s;
    g_dst[i] = d;
    atomicAdd(&g_deg[d], 1);
}

// ---------------- prefix scan (rowptr = exclusive scan of deg) --------------
__global__ void k_scan1() {
    __shared__ int sh[SCANB];
    int tid = threadIdx.x;
    int i = blockIdx.x * SCANB + tid;
    int v = (i < NN) ? g_deg[i] : 0;
    sh[tid] = v;
    __syncthreads();
    for (int off = 1; off < SCANB; off <<= 1) {
        int t = (tid >= off) ? sh[tid - off] : 0;
        __syncthreads();
        sh[tid] += t;
        __syncthreads();
    }
    if (i < NN) g_rowptr[i + 1] = sh[tid];
    if (tid == SCANB - 1) g_bsum[blockIdx.x] = sh[tid];
}

__global__ void k_scan2() {
    if (threadIdx.x == 0) {
        int run = 0;
        for (int b = 0; b < NBLK; b++) { g_boff[b] = run; run += g_bsum[b]; }
    }
}

__global__ void k_scan3() {
    int i = blockIdx.x * blockDim.x + threadIdx.x;
    if (i == 0) g_rowptr[0] = 0;
    if (i < NN) g_rowptr[i + 1] += g_boff[i >> 10];
}

// scatter edges into CSR order (intra-row order nondeterministic; fp-sum
// order already nondeterministic in reference-equivalent atomics — rel_err ok)
__global__ void k_scatter() {
    int e = blockIdx.x * blockDim.x + threadIdx.x;
    if (e >= NE) return;
    int d = g_dst[e];
    int pos = g_rowptr[d] + atomicAdd(&g_woff[d], 1);
    g_esrc[pos] = g_src[e];
}

// ---------------- GEMM: C[M,128] = Aeff[M,K] @ B[K,128] ----------------
// mode 0: A = Aext (x), K=INC,  C = g_h            (GEMM1)
// mode 1: A = (1+eps)*g_h1 + g_agg, K=HIDD, C=Cext (GEMM2, GIN fusion)
__global__ __launch_bounds__(256) void k_gemm(
    const float* __restrict__ Aext, const float* __restrict__ B,
    float* __restrict__ Cext, const float* __restrict__ epsPtr, int mode)
{
    __shared__ float As[16][128];
    __shared__ float Bs[16][128];
    int t  = threadIdx.x;
    int tx = t & 15, ty = t >> 4;
    int blockM = blockIdx.x * 128;

    const float* A  = (mode == 0) ? Aext : g_h1;
    const float* A2 = (mode == 0) ? nullptr : g_agg;
    float*       C  = (mode == 0) ? g_h : Cext;
    int          K  = (mode == 0) ? INC : HIDD;
    float ke = 1.0f;
    if (mode == 1) ke = 1.0f + __ldg(epsPtr);

    float acc[8][8];
#pragma unroll
    for (int r = 0; r < 8; r++)
#pragma unroll
        for (int c = 0; c < 8; c++) acc[r][c] = 0.0f;

    for (int kk = 0; kk < K; kk += 16) {
#pragma unroll
        for (int i = 0; i < 2; i++) {
            int li = t + i * 256;
            int aRow = li >> 2;
            int aC   = (li & 3) * 4;
            int gRow = blockM + aRow;
            float4 v = make_float4(0.f, 0.f, 0.f, 0.f);
            if (gRow < NN) {
                v = *(const float4*)(A + (size_t)gRow * K + kk + aC);
                if (A2) {
                    float4 w = *(const float4*)(A2 + (size_t)gRow * K + kk + aC);
                    v.x = ke * v.x + w.x; v.y = ke * v.y + w.y;
                    v.z = ke * v.z + w.z; v.w = ke * v.w + w.w;
                }
            }
            As[aC + 0][aRow] = v.x; As[aC + 1][aRow] = v.y;
            As[aC + 2][aRow] = v.z; As[aC + 3][aRow] = v.w;
        }
#pragma unroll
        for (int i = 0; i < 2; i++) {
            int li = t + i * 256;
            int bRow = li >> 5;
            int bC   = (li & 31) * 4;
            float4 v = *(const float4*)(B + (size_t)(kk + bRow) * HIDD + bC);
            *(float4*)&Bs[bRow][bC] = v;
        }
        __syncthreads();
#pragma unroll
        for (int k = 0; k < 16; k++) {
            float ra[8], rb[8];
#pragma unroll
            for (int r = 0; r < 8; r++) ra[r] = As[k][ty * 8 + r];
#pragma unroll
            for (int c = 0; c < 8; c++) rb[c] = Bs[k][tx * 8 + c];
#pragma unroll
            for (int r = 0; r < 8; r++)
#pragma unroll
                for (int c = 0; c < 8; c++) acc[r][c] += ra[r] * rb[c];
        }
        __syncthreads();
    }
#pragma unroll
    for (int r = 0; r < 8; r++) {
        int gRow = blockM + ty * 8 + r;
        if (gRow < NN) {
            float4 v0 = make_float4(acc[r][0], acc[r][1], acc[r][2], acc[r][3]);
            float4 v1 = make_float4(acc[r][4], acc[r][5], acc[r][6], acc[r][7]);
            *(float4*)(C + (size_t)gRow * HIDD + tx * 8)     = v0;
            *(float4*)(C + (size_t)gRow * HIDD + tx * 8 + 4) = v1;
        }
    }
}

// ---------------- attention logits per node ----------------
__global__ void k_att(const float* __restrict__ att_s, const float* __restrict__ att_d) {
    int t = blockIdx.x * blockDim.x + threadIdx.x;
    if (t >= NN * HEADS) return;
    int n = t >> 2, head = t & 3;
    const float4* hp  = (const float4*)(g_h + (size_t)n * HIDD + head * CHEAD);
    const float4* asp = (const float4*)(att_s + head * CHEAD);
    const float4* adp = (const float4*)(att_d + head * CHEAD);
    float ss = 0.f, sd = 0.f;
#pragma unroll
    for (int i = 0; i < 8; i++) {
        float4 hv = hp[i], a = asp[i], b = adp[i];
        ss += hv.x * a.x + hv.y * a.y + hv.z * a.z + hv.w * a.w;
        sd += hv.x * b.x + hv.y * b.y + hv.z * b.z + hv.w * b.w;
    }
    g_asrc[t] = ss;
    g_adst[t] = sd;
}

// ---------------- GAT: fused segment softmax + aggregation (warp/dst) -------
// out1[d] = (sum_e exp(e_e - m_d) * h[src_e]) / den_d   -- no atomics
__global__ __launch_bounds__(256) void k_gat_csr() {
    int gw   = (blockIdx.x * blockDim.x + threadIdx.x) >> 5;
    int lane = threadIdx.x & 31;
    if (gw >= NN) return;
    int d  = gw;
    int r0 = g_rowptr[d], r1 = g_rowptr[d + 1];

    float4 ad = *(const float4*)(g_adst + d * 4);

    if (r0 == r1) {   // empty segment -> zeros
        *(float4*)(g_out1 + (size_t)d * HIDD + lane * 4) = make_float4(0.f, 0.f, 0.f, 0.f);
        return;
    }

    // pass 1: per-head max over edges (lane-parallel)
    float4 m = make_float4(-INFINITY, -INFINITY, -INFINITY, -INFINITY);
    for (int i = r0 + lane; i < r1; i += 32) {
        int s = g_esrc[i];
        float4 a = *(const float4*)(g_asrc + s * 4);
        m.x = fmaxf(m.x, lrelu(a.x + ad.x));
        m.y = fmaxf(m.y, lrelu(a.y + ad.y));
        m.z = fmaxf(m.z, lrelu(a.z + ad.z));
        m.w = fmaxf(m.w, lrelu(a.w + ad.w));
    }
#pragma unroll
    for (int off = 16; off; off >>= 1) {
        m.x = fmaxf(m.x, __shfl_xor_sync(0xffffffffu, m.x, off));
        m.y = fmaxf(m.y, __shfl_xor_sync(0xffffffffu, m.y, off));
        m.z = fmaxf(m.z, __shfl_xor_sync(0xffffffffu, m.z, off));
        m.w = fmaxf(m.w, __shfl_xor_sync(0xffffffffu, m.w, off));
    }

    int head = lane >> 3;
    float mh = (head == 0) ? m.x : (head == 1) ? m.y : (head == 2) ? m.z : m.w;
    float adh = (head == 0) ? ad.x : (head == 1) ? ad.y : (head == 2) ? ad.z : ad.w;

    // pass 2: edge-serial, warp-cooperative accumulate num * h[src]
    float4 acc = make_float4(0.f, 0.f, 0.f, 0.f);
    float den = 0.f;
    for (int i = r0; i < r1; i++) {
        int s = g_esrc[i];                               // broadcast
        float ah = __ldg(g_asrc + s * 4 + head);         // 4B per lane, dup x8
        float num = expf(lrelu(ah + adh) - mh);
        den += num;
        float4 hv = *(const float4*)(g_h + (size_t)s * HIDD + lane * 4);
        acc.x += num * hv.x; acc.y += num * hv.y;
        acc.z += num * hv.z; acc.w += num * hv.w;
    }
    float inv = 1.0f / den;
    acc.x *= inv; acc.y *= inv; acc.z *= inv; acc.w *= inv;
    *(float4*)(g_out1 + (size_t)d * HIDD + lane * 4) = acc;
}

// ---------------- GIN neighbor sum (warp/dst, no atomics) -------------------
__global__ __launch_bounds__(256) void k_gin_csr() {
    int gw   = (blockIdx.x * blockDim.x + threadIdx.x) >> 5;
    int lane = threadIdx.x & 31;
    if (gw >= NN) return;
    int d  = gw;
    int r0 = g_rowptr[d], r1 = g_rowptr[d + 1];
    float4 acc = make_float4(0.f, 0.f, 0.f, 0.f);
    for (int i = r0; i < r1; i++) {
        int s = g_esrc[i];
        float4 hv = *(const float4*)(g_h1 + (size_t)s * HIDD + lane * 4);
        acc.x += hv.x; acc.y += hv.y; acc.z += hv.z; acc.w += hv.w;
    }
    *(float4*)(g_agg + (size_t)d * HIDD + lane * 4) = acc;
}

// ---------------- batch norm ----------------
// mode 0: X = g_out1 ; mode 1: X = Xext (harness out buffer)
__global__ void k_bn_stats(const float* __restrict__ Xext, int mode) {
    const float* X = (mode == 0) ? g_out1 : Xext;
    int c = threadIdx.x;                 // 128 threads = one channel each
    int rowsPer = (NN + gridDim.x - 1) / gridDim.x;
    int r0 = blockIdx.x * rowsPer;
    int r1 = r0 + rowsPer; if (r1 > NN) r1 = NN;
    float s = 0.f, q = 0.f;
    for (int r = r0; r < r1; r++) {
        float v = X[(size_t)r * HIDD + c];
        s += v; q += v * v;
    }
    atomicAdd(&g_sum[c], s);
    atomicAdd(&g_sumsq[c], q);
}

__global__ void k_bn_final(const float* __restrict__ gamma, const float* __restrict__ beta) {
    int c = threadIdx.x;
    float mean = g_sum[c] / (float)NN;
    float var  = g_sumsq[c] / (float)NN - mean * mean;
    float sc   = gamma[c] * rsqrtf(var + BN_EPS);
    g_scale[c] = sc;
    g_shift[c] = beta[c] - mean * sc;
    g_sum[c] = 0.f;                      // leave zeroed for next stats pass
    g_sumsq[c] = 0.f;
}

// mode 0: g_out1 -> g_h1 ; mode 1: Xext -> Yext (out, in place)
__global__ void k_bn_apply_elu(const float* __restrict__ Xext, float* __restrict__ Yext, int mode) {
    const float* X = (mode == 0) ? g_out1 : Xext;
    float*       Y = (mode == 0) ? g_h1   : Yext;
    size_t i = (size_t)blockIdx.x * blockDim.x + threadIdx.x;   // NN*HIDD/4 threads
    int c4 = (int)(i & 31);
    float4 v  = ((const float4*)X)[i];
    float4 sc = ((const float4*)g_scale)[c4];
    float4 sh = ((const float4*)g_shift)[c4];
    float4 o;
    o.x = elu(v.x * sc.x + sh.x);
    o.y = elu(v.y * sc.y + sh.y);
    o.z = elu(v.z * sc.z + sh.z);
    o.w = elu(v.w * sc.w + sh.w);
    ((float4*)Y)[i] = o;
}

// ---------------- launch ----------------
extern "C" void kernel_launch(void* const* d_in, const int* in_sizes, int n_in,
                              void* d_out, int out_size) {
    const float* x         = (const float*)d_in[0];
    const float* W_gat     = (const float*)d_in[1];
    const float* att_src   = (const float*)d_in[2];
    const float* att_dst   = (const float*)d_in[3];
    // d_in[4] = bias_gat  : cancels inside BN1 (per-channel shift) -> unused
    const float* bn1_gamma = (const float*)d_in[5];
    const float* bn1_beta  = (const float*)d_in[6];
    const float* eps_gin   = (const float*)d_in[7];
    const float* lin_W     = (const float*)d_in[8];
    // d_in[9] = lin_b     : cancels inside BN2 -> unused
    const float* bn2_gamma = (const float*)d_in[10];
    const float* bn2_beta  = (const float*)d_in[11];
    const void*  edge_idx  = d_in[12];
    float* out = (float*)d_out;

    k_init<<<(NN + 255) / 256, 256>>>();
    k_detect<<<1, 256>>>((const long long*)edge_idx);
    k_edgecvt<<<NE / 256, 256>>>(edge_idx);

    // CSR build
    k_scan1<<<NBLK, SCANB>>>();
    k_scan2<<<1, 32>>>();
    k_scan3<<<(NN + 255) / 256, 256>>>();
    k_scatter<<<NE / 256, 256>>>();

    // GEMM1: g_h = x @ W_gat
    k_gemm<<<(NN + 127) / 128, 256>>>(x, W_gat, nullptr, nullptr, 0);

    // attention logits per node
    k_att<<<(NN * HEADS + 255) / 256, 256>>>(att_src, att_dst);

    // GAT fused softmax + message aggregation (warp per dst)
    k_gat_csr<<<(NN * 32 + 255) / 256, 256>>>();

    // BN1 + ELU -> g_h1
    k_bn_stats<<<400, 128>>>(nullptr, 0);
    k_bn_final<<<1, 128>>>(bn1_gamma, bn1_beta);
    k_bn_apply_elu<<<(NN * HIDD / 4) / 256, 256>>>(nullptr, nullptr, 0);

    // GIN aggregation (warp per dst)
    k_gin_csr<<<(NN * 32 + 255) / 256, 256>>>();

    // GEMM2 on fused z = (1+eps)*g_h1 + g_agg  -> d_out (pre-BN2)
    k_gemm<<<(NN + 127) / 128, 256>>>(nullptr, lin_W, out, eps_gin, 1);

    // BN2 + ELU in place on d_out
    k_bn_stats<<<400, 128>>>(out, 1);
    k_bn_final<<<1, 128>>>(bn2_gamma, bn2_beta);
    k_bn_apply_elu<<<(NN * HIDD / 4) / 256, 256>>>(out, out, 1);
}